// round 2
// baseline (speedup 1.0000x reference)
#include <cuda_runtime.h>
#include <cstdint>

#define B_   512
#define L_   1024
#define K_   8
#define NR_  512
#define S_   20
#define EXT_ 26
#define SQN  6
#define NTAY 8      // Taylor order (ref uses 16; ||A||<=~0.27 -> order-8 error ~1e-11)
#define LT   128    // l-positions per writer block
#define WTH  416    // writer threads: 8 positions x 52 float4 lanes

// Scratch (device globals; no allocation allowed)
__device__ __align__(16) float g_Q[K_ * S_ * S_];                 // 12.8 KB
__device__ __align__(16) float g_P[(size_t)NR_ * K_ * S_ * S_];   // 6.55 MB
__device__ unsigned int g_used[NR_];

__device__ __forceinline__ float softplus_f(float x) {
    return fmaxf(x, 0.0f) + log1pf(expf(-fabsf(x)));
}

// ---------------------------------------------------------------------------
// Kernel A: build Q[k] (8 blocks of 20x20 threads)
// ---------------------------------------------------------------------------
__global__ void qprep_kernel(const float* __restrict__ exch,
                             const float* __restrict__ freq) {
    const int k = blockIdx.x;
    const int i = threadIdx.y;
    const int j = threadIdx.x;

    __shared__ float Rs[S_][S_ + 1];
    __shared__ float diag[S_];
    __shared__ float fr[S_];

    if (i == 0) fr[j] = freq[j];

    float e1 = exch[(k * S_ + i) * S_ + j];
    float e2 = exch[(k * S_ + j) * S_ + i];
    float r = softplus_f(0.5f * (e1 + e2));
    if (i == j) r = 0.0f;
    __syncthreads();

    float q = r * fr[j];
    Rs[i][j] = q;
    __syncthreads();

    if (j == 0) {
        float d = 0.0f;
        #pragma unroll
        for (int t = 0; t < S_; t++) d += Rs[i][t];
        diag[i] = d;
    }
    __syncthreads();

    float mue = 0.0f;
    #pragma unroll
    for (int t = 0; t < S_; t++) mue += fr[t] * diag[t];
    mue = fmaxf(mue, 1e-16f);

    float val = q - (i == j ? diag[i] : 0.0f);
    g_Q[(k * S_ + i) * S_ + j] = val / mue;
}

// ---------------------------------------------------------------------------
// used-rate marking
// ---------------------------------------------------------------------------
__global__ void clear_used_kernel() {
    int r = blockIdx.x * blockDim.x + threadIdx.x;
    if (r < NR_) g_used[r] = 0u;
}
__global__ void mark_used_kernel(const int* __restrict__ rate_indices) {
    int b = blockIdx.x * blockDim.x + threadIdx.x;
    if (b < B_) g_used[rate_indices[b]] = 1u;
}

// ---------------------------------------------------------------------------
// Kernel C: expm, one WARP per (r,k) matrix. Rows of T/P live in registers
// (lane i owns row i); the right-hand operand is broadcast-read from smem.
// Scaling 2^-6 + Taylor order NTAY + 6 squarings.
// ---------------------------------------------------------------------------
__global__ void __launch_bounds__(256)
expm_warp_kernel(const float* __restrict__ tau_kernel) {
    const int warp = threadIdx.x >> 5;
    const int lane = threadIdx.x & 31;
    const int m = blockIdx.x * 8 + warp;          // matrix id = r*K + k
    const int r = m >> 3;
    const int k = m & 7;
    if (!g_used[r]) return;

    __shared__ __align__(16) float sh[8][S_ * S_];   // per-warp 20x20 tile
    float* Ash = sh[warp];

    const float tau = softplus_f(tau_kernel[r]);
    const float scale = tau * (1.0f / 64.0f);

    float a[S_];      // this lane's row of A (zeros for lanes >= 20)
    float Trow[S_];   // row of Taylor term
    float Prow[S_];   // row of accumulator P

    #pragma unroll
    for (int j = 0; j < S_; j++) a[j] = 0.0f;

    if (lane < S_) {
        const float4* src = (const float4*)(g_Q + (k * S_ + lane) * S_);
        float4* dst = (float4*)(Ash + lane * S_);
        #pragma unroll
        for (int w = 0; w < S_ / 4; w++) {
            float4 v = src[w];
            v.x *= scale; v.y *= scale; v.z *= scale; v.w *= scale;
            dst[w] = v;
            a[4 * w + 0] = v.x; a[4 * w + 1] = v.y;
            a[4 * w + 2] = v.z; a[4 * w + 3] = v.w;
        }
    }
    #pragma unroll
    for (int j = 0; j < S_; j++) {
        Trow[j] = a[j];
        Prow[j] = a[j] + ((lane == j) ? 1.0f : 0.0f);
    }
    __syncwarp();

    // Taylor: T = T*A/n ; P += T
    #pragma unroll 1
    for (int n = 2; n <= NTAY; n++) {
        float acc[S_];
        #pragma unroll
        for (int j = 0; j < S_; j++) acc[j] = 0.0f;
        #pragma unroll
        for (int t = 0; t < S_; t++) {
            const float4* At = (const float4*)(Ash + t * S_);
            const float Tt = Trow[t];
            #pragma unroll
            for (int w = 0; w < S_ / 4; w++) {
                float4 v = At[w];          // broadcast load
                acc[4 * w + 0] = fmaf(Tt, v.x, acc[4 * w + 0]);
                acc[4 * w + 1] = fmaf(Tt, v.y, acc[4 * w + 1]);
                acc[4 * w + 2] = fmaf(Tt, v.z, acc[4 * w + 2]);
                acc[4 * w + 3] = fmaf(Tt, v.w, acc[4 * w + 3]);
            }
        }
        const float inv = 1.0f / (float)n;
        #pragma unroll
        for (int j = 0; j < S_; j++) {
            Trow[j] = acc[j] * inv;
            Prow[j] += Trow[j];
        }
    }

    // 6 squarings: P = P*P (write P rows to smem, broadcast-read)
    #pragma unroll 1
    for (int q = 0; q < SQN; q++) {
        __syncwarp();
        if (lane < S_) {
            float4* dst = (float4*)(Ash + lane * S_);
            #pragma unroll
            for (int w = 0; w < S_ / 4; w++) {
                float4 v;
                v.x = Prow[4 * w + 0]; v.y = Prow[4 * w + 1];
                v.z = Prow[4 * w + 2]; v.w = Prow[4 * w + 3];
                dst[w] = v;
            }
        }
        __syncwarp();
        float acc[S_];
        #pragma unroll
        for (int j = 0; j < S_; j++) acc[j] = 0.0f;
        #pragma unroll
        for (int t = 0; t < S_; t++) {
            const float4* Pt = (const float4*)(Ash + t * S_);
            const float pt = Prow[t];
            #pragma unroll
            for (int w = 0; w < S_ / 4; w++) {
                float4 v = Pt[w];
                acc[4 * w + 0] = fmaf(pt, v.x, acc[4 * w + 0]);
                acc[4 * w + 1] = fmaf(pt, v.y, acc[4 * w + 1]);
                acc[4 * w + 2] = fmaf(pt, v.z, acc[4 * w + 2]);
                acc[4 * w + 3] = fmaf(pt, v.w, acc[4 * w + 3]);
            }
        }
        #pragma unroll
        for (int j = 0; j < S_; j++) Prow[j] = acc[j];
    }

    if (lane < S_) {
        float4* dst = (float4*)(g_P + (size_t)m * (S_ * S_) + lane * S_);
        #pragma unroll
        for (int w = 0; w < S_ / 4; w++) {
            float4 v;
            v.x = Prow[4 * w + 0]; v.y = Prow[4 * w + 1];
            v.z = Prow[4 * w + 2]; v.w = Prow[4 * w + 3];
            dst[w] = v;
        }
    }
}

// ---------------------------------------------------------------------------
// Kernel D: bandwidth kernel. Per (b, 128-l strip) block:
//  build RowTable[26][208] in smem (all possible output rows for this b),
//  then pure coalesced LDS.128 -> STG.128 streaming copy.
// ---------------------------------------------------------------------------
__global__ void __launch_bounds__(WTH) writer_kernel(
        const int* __restrict__ inputs,
        const int* __restrict__ rate_indices,
        float* __restrict__ out) {
    const int b  = blockIdx.y;
    const int l0 = blockIdx.x * LT;
    const int tid = threadIdx.x;

    __shared__ __align__(16) float RT[EXT_ * K_ * EXT_];   // 26 * 208 floats
    __shared__ int cs[LT];

    const int r = rate_indices[b];
    const float* Pr = g_P + (size_t)(r * K_) * (S_ * S_);

    // build row table: RT[c][k*26+e]
    for (int idx = tid; idx < EXT_ * K_ * EXT_; idx += WTH) {
        const int c = idx / (K_ * EXT_);
        const int f = idx - c * (K_ * EXT_);
        const int kk = f / EXT_;
        const int e  = f - kk * EXT_;
        float v;
        if (c < S_) {
            v = (e < S_) ? Pr[kk * (S_ * S_) + c * S_ + e] : 0.0f;
        } else {
            v = (e == c) ? 1.0f : 0.0f;
        }
        RT[idx] = v;
    }
    for (int t = tid; t < LT; t += WTH)
        cs[t] = inputs[b * L_ + l0 + t];
    __syncthreads();

    const int j  = tid % 52;     // float4 lane within the 208-float row
    const int p0 = tid / 52;     // 0..7
    const float4* RT4 = (const float4*)RT;
    float4* ob = (float4*)out + ((size_t)b * L_ + l0) * 52;

    #pragma unroll 4
    for (int p = p0; p < LT; p += 8) {
        const int c = cs[p];
        float4 v = RT4[c * 52 + j];
        __stcs(ob + (size_t)p * 52 + j, v);
    }
}

// ---------------------------------------------------------------------------
extern "C" void kernel_launch(void* const* d_in, const int* in_sizes, int n_in,
                              void* d_out, int out_size) {
    const int*   inputs       = (const int*)  d_in[0];
    const int*   rate_indices = (const int*)  d_in[1];
    const float* tau_kernel   = (const float*)d_in[2];
    const float* exch         = (const float*)d_in[3];
    const float* freq         = (const float*)d_in[4];
    float*       out          = (float*)d_out;

    (void)in_sizes; (void)n_in; (void)out_size;

    dim3 tb(S_, S_);
    qprep_kernel<<<K_, tb>>>(exch, freq);
    clear_used_kernel<<<(NR_ + 255) / 256, 256>>>();
    mark_used_kernel<<<(B_ + 255) / 256, 256>>>(rate_indices);
    expm_warp_kernel<<<NR_ * K_ / 8, 256>>>(tau_kernel);

    dim3 grid(L_ / LT, B_);
    writer_kernel<<<grid, WTH>>>(inputs, rate_indices, out);
}

// round 3
// speedup vs baseline: 4.9970x; 4.9970x over previous
#include <cuda_runtime.h>
#include <cstdint>

#define B_   512
#define L_   1024
#define K_   8
#define NR_  512
#define S_   20
#define EXT_ 26
#define SQN  6
#define NTAY 8      // ||A|| <= ~0.27 -> order-8 Taylor error ~1e-11 (validated R1->R2)
#define LT   128
#define WTH  416
#define MPB  4      // matrices per expm block (all share the same r)

// Scratch (device globals; no allocation allowed)
__device__ __align__(16) float g_Q[K_ * S_ * S_];
__device__ __align__(16) float g_P[(size_t)NR_ * K_ * S_ * S_];
__device__ unsigned int g_used[NR_];

__device__ __forceinline__ float softplus_f(float x) {
    return fmaxf(x, 0.0f) + log1pf(expf(-fabsf(x)));
}

// ---------------------------------------------------------------------------
// Kernel A: build Q[k] (8 blocks of 20x20 threads)
// ---------------------------------------------------------------------------
__global__ void qprep_kernel(const float* __restrict__ exch,
                             const float* __restrict__ freq) {
    const int k = blockIdx.x;
    const int i = threadIdx.y;
    const int j = threadIdx.x;

    __shared__ float Rs[S_][S_ + 1];
    __shared__ float diag[S_];
    __shared__ float fr[S_];

    if (i == 0) fr[j] = freq[j];

    float e1 = exch[(k * S_ + i) * S_ + j];
    float e2 = exch[(k * S_ + j) * S_ + i];
    float r = softplus_f(0.5f * (e1 + e2));
    if (i == j) r = 0.0f;
    __syncthreads();

    float q = r * fr[j];
    Rs[i][j] = q;
    __syncthreads();

    if (j == 0) {
        float d = 0.0f;
        #pragma unroll
        for (int t = 0; t < S_; t++) d += Rs[i][t];
        diag[i] = d;
    }
    __syncthreads();

    float mue = 0.0f;
    #pragma unroll
    for (int t = 0; t < S_; t++) mue += fr[t] * diag[t];
    mue = fmaxf(mue, 1e-16f);

    float val = q - (i == j ? diag[i] : 0.0f);
    g_Q[(k * S_ + i) * S_ + j] = val / mue;
}

// ---------------------------------------------------------------------------
// used-rate marking
// ---------------------------------------------------------------------------
__global__ void clear_used_kernel() {
    int r = blockIdx.x * blockDim.x + threadIdx.x;
    if (r < NR_) g_used[r] = 0u;
}
__global__ void mark_used_kernel(const int* __restrict__ rate_indices) {
    int b = blockIdx.x * blockDim.x + threadIdx.x;
    if (b < B_) g_used[rate_indices[b]] = 1u;
}

// ---------------------------------------------------------------------------
// Kernel C v3: expm with NO per-thread arrays (only one float4 accumulator).
// Thread (i, jv) owns output elements (i, 4*jv .. 4*jv+3) of one matrix.
// 128-thread slot per matrix, 4 matrices (same r) per 512-thread block.
// ---------------------------------------------------------------------------
__global__ void __launch_bounds__(512)
expm_v3_kernel(const float* __restrict__ tau_kernel) {
    const int tid  = threadIdx.x;
    const int slot = tid >> 7;            // matrix slot 0..3
    const int t    = tid & 127;
    const int m    = blockIdx.x * MPB + slot;   // m = r*8 + k
    const int r    = blockIdx.x >> 1;           // same for all threads in block
    const int k    = m & 7;
    if (!g_used[r]) return;               // block-uniform

    const int  i      = t / 5;            // row 0..19 (when active)
    const int  jv     = t - i * 5;        // float4 column group 0..4
    const bool active = (t < 100);

    __shared__ __align__(16) float Ash[MPB][S_ * S_];
    __shared__ __align__(16) float Tsh[MPB][2][S_ * S_];

    const float tau   = softplus_f(tau_kernel[r]);
    const float scale = tau * (1.0f / 64.0f);

    // P accumulator for this thread's 4 elements (register-resident, no array)
    float4 P = make_float4(0.f, 0.f, 0.f, 0.f);

    if (active) {
        float4 q = *(const float4*)(g_Q + (k * S_ + i) * S_ + jv * 4);
        float4 a = make_float4(q.x * scale, q.y * scale, q.z * scale, q.w * scale);
        *(float4*)(&Ash[slot][i * S_ + jv * 4])    = a;
        *(float4*)(&Tsh[slot][0][i * S_ + jv * 4]) = a;
        // P = I + A
        const int j0 = jv * 4;
        P.x = a.x + (i == j0 + 0 ? 1.f : 0.f);
        P.y = a.y + (i == j0 + 1 ? 1.f : 0.f);
        P.z = a.z + (i == j0 + 2 ? 1.f : 0.f);
        P.w = a.w + (i == j0 + 3 ? 1.f : 0.f);
    }
    __syncthreads();

    // Taylor: T <- T*A/n ; P += T
    int cur = 0;
    #pragma unroll 1
    for (int n = 2; n <= NTAY; n++) {
        float4 acc = make_float4(0.f, 0.f, 0.f, 0.f);
        if (active) {
            const float* Trow = &Tsh[slot][cur][i * S_];
            #pragma unroll
            for (int tt = 0; tt < S_; tt++) {
                const float  Tt = Trow[tt];                                  // broadcast
                const float4 A4 = *(const float4*)(&Ash[slot][tt * S_ + jv * 4]);
                acc.x = fmaf(Tt, A4.x, acc.x);
                acc.y = fmaf(Tt, A4.y, acc.y);
                acc.z = fmaf(Tt, A4.z, acc.z);
                acc.w = fmaf(Tt, A4.w, acc.w);
            }
            const float inv = 1.0f / (float)n;
            acc.x *= inv; acc.y *= inv; acc.z *= inv; acc.w *= inv;
            *(float4*)(&Tsh[slot][cur ^ 1][i * S_ + jv * 4]) = acc;
            P.x += acc.x; P.y += acc.y; P.z += acc.z; P.w += acc.w;
        }
        cur ^= 1;
        __syncthreads();
    }

    // 6 squarings: P <- P*P  (stage P in Tsh[slot][0])
    #pragma unroll 1
    for (int q = 0; q < SQN; q++) {
        if (active)
            *(float4*)(&Tsh[slot][0][i * S_ + jv * 4]) = P;
        __syncthreads();
        if (active) {
            float4 acc = make_float4(0.f, 0.f, 0.f, 0.f);
            const float* Prow = &Tsh[slot][0][i * S_];
            #pragma unroll
            for (int tt = 0; tt < S_; tt++) {
                const float  pt = Prow[tt];
                const float4 P4 = *(const float4*)(&Tsh[slot][0][tt * S_ + jv * 4]);
                acc.x = fmaf(pt, P4.x, acc.x);
                acc.y = fmaf(pt, P4.y, acc.y);
                acc.z = fmaf(pt, P4.z, acc.z);
                acc.w = fmaf(pt, P4.w, acc.w);
            }
            P = acc;
        }
        __syncthreads();
    }

    if (active)
        *(float4*)(g_P + (size_t)m * (S_ * S_) + i * S_ + jv * 4) = P;
}

// ---------------------------------------------------------------------------
// Kernel D: bandwidth kernel (unchanged from R2: RowTable + streaming copy)
// ---------------------------------------------------------------------------
__global__ void __launch_bounds__(WTH) writer_kernel(
        const int* __restrict__ inputs,
        const int* __restrict__ rate_indices,
        float* __restrict__ out) {
    const int b  = blockIdx.y;
    const int l0 = blockIdx.x * LT;
    const int tid = threadIdx.x;

    __shared__ __align__(16) float RT[EXT_ * K_ * EXT_];
    __shared__ int cs[LT];

    const int r = rate_indices[b];
    const float* Pr = g_P + (size_t)(r * K_) * (S_ * S_);

    for (int idx = tid; idx < EXT_ * K_ * EXT_; idx += WTH) {
        const int c = idx / (K_ * EXT_);
        const int f = idx - c * (K_ * EXT_);
        const int kk = f / EXT_;
        const int e  = f - kk * EXT_;
        float v;
        if (c < S_) {
            v = (e < S_) ? Pr[kk * (S_ * S_) + c * S_ + e] : 0.0f;
        } else {
            v = (e == c) ? 1.0f : 0.0f;
        }
        RT[idx] = v;
    }
    for (int tt = tid; tt < LT; tt += WTH)
        cs[tt] = inputs[b * L_ + l0 + tt];
    __syncthreads();

    const int j  = tid % 52;
    const int p0 = tid / 52;
    const float4* RT4 = (const float4*)RT;
    float4* ob = (float4*)out + ((size_t)b * L_ + l0) * 52;

    #pragma unroll 4
    for (int p = p0; p < LT; p += 8) {
        const int c = cs[p];
        float4 v = RT4[c * 52 + j];
        __stcs(ob + (size_t)p * 52 + j, v);
    }
}

// ---------------------------------------------------------------------------
extern "C" void kernel_launch(void* const* d_in, const int* in_sizes, int n_in,
                              void* d_out, int out_size) {
    const int*   inputs       = (const int*)  d_in[0];
    const int*   rate_indices = (const int*)  d_in[1];
    const float* tau_kernel   = (const float*)d_in[2];
    const float* exch         = (const float*)d_in[3];
    const float* freq         = (const float*)d_in[4];
    float*       out          = (float*)d_out;

    (void)in_sizes; (void)n_in; (void)out_size;

    dim3 tb(S_, S_);
    qprep_kernel<<<K_, tb>>>(exch, freq);
    clear_used_kernel<<<(NR_ + 255) / 256, 256>>>();
    mark_used_kernel<<<(B_ + 255) / 256, 256>>>(rate_indices);
    expm_v3_kernel<<<NR_ * K_ / MPB, 512>>>(tau_kernel);

    dim3 grid(L_ / LT, B_);
    writer_kernel<<<grid, WTH>>>(inputs, rate_indices, out);
}

// round 4
// speedup vs baseline: 5.2041x; 1.0414x over previous
#include <cuda_runtime.h>
#include <cstdint>

#define B_   512
#define L_   1024
#define K_   8
#define NR_  512
#define S_   20
#define EXT_ 26
#define SQN  6
#define NTAY 8      // ||A|| <= ~0.27 -> order-8 Taylor error ~1e-11 (validated)
#define LT   128
#define WTH  416
#define WPB  8      // warps (matrices) per expm block

// Scratch (device globals; no allocation allowed)
__device__ __align__(16) float g_Q[K_ * S_ * S_];
__device__ __align__(16) float g_P[(size_t)NR_ * K_ * S_ * S_];
__device__ unsigned int g_used[NR_];

__device__ __forceinline__ float softplus_f(float x) {
    return fmaxf(x, 0.0f) + log1pf(expf(-fabsf(x)));
}

// ---------------------------------------------------------------------------
// Kernel A: build Q[k] (8 blocks of 20x20 threads)
// ---------------------------------------------------------------------------
__global__ void qprep_kernel(const float* __restrict__ exch,
                             const float* __restrict__ freq) {
    const int k = blockIdx.x;
    const int i = threadIdx.y;
    const int j = threadIdx.x;

    __shared__ float Rs[S_][S_ + 1];
    __shared__ float diag[S_];
    __shared__ float fr[S_];

    if (i == 0) fr[j] = freq[j];

    float e1 = exch[(k * S_ + i) * S_ + j];
    float e2 = exch[(k * S_ + j) * S_ + i];
    float r = softplus_f(0.5f * (e1 + e2));
    if (i == j) r = 0.0f;
    __syncthreads();

    float q = r * fr[j];
    Rs[i][j] = q;
    __syncthreads();

    if (j == 0) {
        float d = 0.0f;
        #pragma unroll
        for (int t = 0; t < S_; t++) d += Rs[i][t];
        diag[i] = d;
    }
    __syncthreads();

    float mue = 0.0f;
    #pragma unroll
    for (int t = 0; t < S_; t++) mue += fr[t] * diag[t];
    mue = fmaxf(mue, 1e-16f);

    float val = q - (i == j ? diag[i] : 0.0f);
    g_Q[(k * S_ + i) * S_ + j] = val / mue;
}

// ---------------------------------------------------------------------------
// used-rate marking
// ---------------------------------------------------------------------------
__global__ void clear_used_kernel() {
    int r = blockIdx.x * blockDim.x + threadIdx.x;
    if (r < NR_) g_used[r] = 0u;
}
__global__ void mark_used_kernel(const int* __restrict__ rate_indices) {
    int b = blockIdx.x * blockDim.x + threadIdx.x;
    if (b < B_) g_used[rate_indices[b]] = 1u;
}

// ---------------------------------------------------------------------------
// Kernel C v4: one WARP per matrix, thread owns a 4x4 output tile.
// T kept column-major in smem (so T[i..i+3][t] is one LDS.128), A row-major.
// Only __syncwarp; no block barriers.
// ---------------------------------------------------------------------------
__global__ void __launch_bounds__(32 * WPB)
expm_v4_kernel(const float* __restrict__ tau_kernel) {
    const int lane = threadIdx.x & 31;
    const int w    = threadIdx.x >> 5;
    const int m    = blockIdx.x * WPB + w;      // matrix id = r*8 + k
    const int r    = m >> 3;
    const int k    = m & 7;
    if (!g_used[r]) return;                     // warp-uniform

    const bool act = (lane < 25);
    const int  a   = lane / 5;                  // tile-row 0..4 (rows 4a..4a+3)
    const int  b   = lane - a * 5;              // tile-col 0..4 (cols 4b..4b+3)

    __shared__ __align__(16) float sA[WPB][S_ * S_];        // row-major A / P
    __shared__ __align__(16) float sT[WPB][2][S_ * S_];     // column-major T dbl-buf
    float* Arm = sA[w];
    float* Tc  = sT[w][0];
    float* Tn  = sT[w][1];

    const float tau   = softplus_f(tau_kernel[r]);
    const float scale = tau * (1.0f / 64.0f);

    float P[4][4];     // register accumulator (exponential result tile)

    if (act) {
        float4 arow[4];
        #pragma unroll
        for (int r4 = 0; r4 < 4; r4++) {
            float4 q = *(const float4*)(g_Q + (k * S_ + 4 * a + r4) * S_ + 4 * b);
            arow[r4] = make_float4(q.x * scale, q.y * scale, q.z * scale, q.w * scale);
            *(float4*)(Arm + (4 * a + r4) * S_ + 4 * b) = arow[r4];
        }
        // column-major copy of A into Tc
        {
            float4 c0 = make_float4(arow[0].x, arow[1].x, arow[2].x, arow[3].x);
            float4 c1 = make_float4(arow[0].y, arow[1].y, arow[2].y, arow[3].y);
            float4 c2 = make_float4(arow[0].z, arow[1].z, arow[2].z, arow[3].z);
            float4 c3 = make_float4(arow[0].w, arow[1].w, arow[2].w, arow[3].w);
            *(float4*)(Tc + (4 * b + 0) * S_ + 4 * a) = c0;
            *(float4*)(Tc + (4 * b + 1) * S_ + 4 * a) = c1;
            *(float4*)(Tc + (4 * b + 2) * S_ + 4 * a) = c2;
            *(float4*)(Tc + (4 * b + 3) * S_ + 4 * a) = c3;
        }
        // P = I + A
        const float* ar = &arow[0].x;
        #pragma unroll
        for (int r4 = 0; r4 < 4; r4++)
            #pragma unroll
            for (int c = 0; c < 4; c++)
                P[r4][c] = (&arow[r4].x)[c] + ((4 * a + r4) == (4 * b + c) ? 1.0f : 0.0f);
        (void)ar;
    }
    __syncwarp();

    // Taylor: T <- T*A/n ; P += T     (reads Tc + Arm, writes Tn)
    #pragma unroll 1
    for (int n = 2; n <= NTAY; n++) {
        if (act) {
            float acc[4][4];
            #pragma unroll
            for (int r4 = 0; r4 < 4; r4++)
                #pragma unroll
                for (int c = 0; c < 4; c++) acc[r4][c] = 0.0f;

            #pragma unroll
            for (int t = 0; t < S_; t++) {
                const float4 tv = *(const float4*)(Tc + t * S_ + 4 * a);   // T[4a..][t]
                const float4 av = *(const float4*)(Arm + t * S_ + 4 * b); // A[t][4b..]
                const float* tvp = &tv.x;
                const float* avp = &av.x;
                #pragma unroll
                for (int r4 = 0; r4 < 4; r4++)
                    #pragma unroll
                    for (int c = 0; c < 4; c++)
                        acc[r4][c] = fmaf(tvp[r4], avp[c], acc[r4][c]);
            }
            const float inv = 1.0f / (float)n;
            #pragma unroll
            for (int r4 = 0; r4 < 4; r4++)
                #pragma unroll
                for (int c = 0; c < 4; c++) {
                    acc[r4][c] *= inv;
                    P[r4][c] += acc[r4][c];
                }
            // store acc column-major into Tn
            #pragma unroll
            for (int c = 0; c < 4; c++) {
                float4 v = make_float4(acc[0][c], acc[1][c], acc[2][c], acc[3][c]);
                *(float4*)(Tn + (4 * b + c) * S_ + 4 * a) = v;
            }
        }
        { float* tmp = Tc; Tc = Tn; Tn = tmp; }
        __syncwarp();
    }

    // Squarings: P <- P*P  (stage P row-major in Arm, column-major in Tc)
    #pragma unroll 1
    for (int q = 0; q < SQN; q++) {
        if (act) {
            #pragma unroll
            for (int r4 = 0; r4 < 4; r4++) {
                float4 v = make_float4(P[r4][0], P[r4][1], P[r4][2], P[r4][3]);
                *(float4*)(Arm + (4 * a + r4) * S_ + 4 * b) = v;
            }
            #pragma unroll
            for (int c = 0; c < 4; c++) {
                float4 v = make_float4(P[0][c], P[1][c], P[2][c], P[3][c]);
                *(float4*)(Tc + (4 * b + c) * S_ + 4 * a) = v;
            }
        }
        __syncwarp();
        if (act) {
            float acc[4][4];
            #pragma unroll
            for (int r4 = 0; r4 < 4; r4++)
                #pragma unroll
                for (int c = 0; c < 4; c++) acc[r4][c] = 0.0f;
            #pragma unroll
            for (int t = 0; t < S_; t++) {
                const float4 tv = *(const float4*)(Tc + t * S_ + 4 * a);   // P[4a..][t]
                const float4 av = *(const float4*)(Arm + t * S_ + 4 * b); // P[t][4b..]
                const float* tvp = &tv.x;
                const float* avp = &av.x;
                #pragma unroll
                for (int r4 = 0; r4 < 4; r4++)
                    #pragma unroll
                    for (int c = 0; c < 4; c++)
                        acc[r4][c] = fmaf(tvp[r4], avp[c], acc[r4][c]);
            }
            #pragma unroll
            for (int r4 = 0; r4 < 4; r4++)
                #pragma unroll
                for (int c = 0; c < 4; c++) P[r4][c] = acc[r4][c];
        }
        __syncwarp();
    }

    if (act) {
        float* dst = g_P + (size_t)m * (S_ * S_);
        #pragma unroll
        for (int r4 = 0; r4 < 4; r4++) {
            float4 v = make_float4(P[r4][0], P[r4][1], P[r4][2], P[r4][3]);
            *(float4*)(dst + (4 * a + r4) * S_ + 4 * b) = v;
        }
    }
}

// ---------------------------------------------------------------------------
// Kernel D: bandwidth kernel (RowTable + streaming copy)
// ---------------------------------------------------------------------------
__global__ void __launch_bounds__(WTH) writer_kernel(
        const int* __restrict__ inputs,
        const int* __restrict__ rate_indices,
        float* __restrict__ out) {
    const int b  = blockIdx.y;
    const int l0 = blockIdx.x * LT;
    const int tid = threadIdx.x;

    __shared__ __align__(16) float RT[EXT_ * K_ * EXT_];
    __shared__ int cs[LT];

    const int r = rate_indices[b];
    const float* Pr = g_P + (size_t)(r * K_) * (S_ * S_);

    for (int idx = tid; idx < EXT_ * K_ * EXT_; idx += WTH) {
        const int c = idx / (K_ * EXT_);
        const int f = idx - c * (K_ * EXT_);
        const int kk = f / EXT_;
        const int e  = f - kk * EXT_;
        float v;
        if (c < S_) {
            v = (e < S_) ? Pr[kk * (S_ * S_) + c * S_ + e] : 0.0f;
        } else {
            v = (e == c) ? 1.0f : 0.0f;
        }
        RT[idx] = v;
    }
    for (int tt = tid; tt < LT; tt += WTH)
        cs[tt] = inputs[b * L_ + l0 + tt];
    __syncthreads();

    const int j  = tid % 52;
    const int p0 = tid / 52;
    const float4* RT4 = (const float4*)RT;
    float4* ob = (float4*)out + ((size_t)b * L_ + l0) * 52;

    #pragma unroll 4
    for (int p = p0; p < LT; p += 8) {
        const int c = cs[p];
        float4 v = RT4[c * 52 + j];
        __stcs(ob + (size_t)p * 52 + j, v);
    }
}

// ---------------------------------------------------------------------------
extern "C" void kernel_launch(void* const* d_in, const int* in_sizes, int n_in,
                              void* d_out, int out_size) {
    const int*   inputs       = (const int*)  d_in[0];
    const int*   rate_indices = (const int*)  d_in[1];
    const float* tau_kernel   = (const float*)d_in[2];
    const float* exch         = (const float*)d_in[3];
    const float* freq         = (const float*)d_in[4];
    float*       out          = (float*)d_out;

    (void)in_sizes; (void)n_in; (void)out_size;

    dim3 tb(S_, S_);
    qprep_kernel<<<K_, tb>>>(exch, freq);
    clear_used_kernel<<<(NR_ + 255) / 256, 256>>>();
    mark_used_kernel<<<(B_ + 255) / 256, 256>>>(rate_indices);
    expm_v4_kernel<<<NR_ * K_ / WPB, 32 * WPB>>>(tau_kernel);

    dim3 grid(L_ / LT, B_);
    writer_kernel<<<grid, WTH>>>(inputs, rate_indices, out);
}

// round 5
// speedup vs baseline: 5.6875x; 1.0929x over previous
#include <cuda_runtime.h>
#include <cstdint>

#define B_   512
#define L_   1024
#define K_   8
#define NR_  512
#define S_   20
#define EXT_ 26
#define SQN  6
#define NTAY 8      // ||A|| <= ~0.27 -> order-8 Taylor error ~1e-11 (validated)
#define NTHR 416    // 13 warps: 8 expm warps + 5 fill warps; 416 = 8*52 copy lanes
#define ROWW (K_ * EXT_)   // 208 floats per output row

// Tiny scratch (device global; no allocation allowed)
__device__ __align__(16) float g_Q[K_ * S_ * S_];

__device__ __forceinline__ float softplus_f(float x) {
    return fmaxf(x, 0.0f) + log1pf(expf(-fabsf(x)));
}

// ---------------------------------------------------------------------------
// Kernel A: build Q[k] (8 blocks of 20x20 threads) — unchanged
// ---------------------------------------------------------------------------
__global__ void qprep_kernel(const float* __restrict__ exch,
                             const float* __restrict__ freq) {
    const int k = blockIdx.x;
    const int i = threadIdx.y;
    const int j = threadIdx.x;

    __shared__ float Rs[S_][S_ + 1];
    __shared__ float diag[S_];
    __shared__ float fr[S_];

    if (i == 0) fr[j] = freq[j];

    float e1 = exch[(k * S_ + i) * S_ + j];
    float e2 = exch[(k * S_ + j) * S_ + i];
    float r = softplus_f(0.5f * (e1 + e2));
    if (i == j) r = 0.0f;
    __syncthreads();

    float q = r * fr[j];
    Rs[i][j] = q;
    __syncthreads();

    if (j == 0) {
        float d = 0.0f;
        #pragma unroll
        for (int t = 0; t < S_; t++) d += Rs[i][t];
        diag[i] = d;
    }
    __syncthreads();

    float mue = 0.0f;
    #pragma unroll
    for (int t = 0; t < S_; t++) mue += fr[t] * diag[t];
    mue = fmaxf(mue, 1e-16f);

    float val = q - (i == j ? diag[i] : 0.0f);
    g_Q[(k * S_ + i) * S_ + j] = val / mue;
}

// ---------------------------------------------------------------------------
// FUSED kernel: one block per b. Warps 0-7 compute expm(tau*Q[k]) straight
// into the smem RowTable (warp-per-matrix, 4x4 tiles per lane, single-buffer
// T with __syncwarp). Warps 8-12 fill the pad/one-hot region. Then a pure
// LDS.128 -> STG.128 streaming copy of 1024 rows x 832B.
// ---------------------------------------------------------------------------
__global__ void __launch_bounds__(NTHR)
fused_kernel(const int* __restrict__ inputs,
             const int* __restrict__ rate_indices,
             const float* __restrict__ tau_kernel,
             float* __restrict__ out) {
    const int b    = blockIdx.x;
    const int tid  = threadIdx.x;
    const int w    = tid >> 5;
    const int lane = tid & 31;

    __shared__ __align__(16) float RT[EXT_ * ROWW];   // 26*208 = 5408 f (21.6KB)
    __shared__ __align__(16) float sA[K_][S_ * S_];   // row-major A / P (12.8KB)
    __shared__ __align__(16) float sT[K_][S_ * S_];   // col-major T / P (12.8KB)

    const int   r     = rate_indices[b];
    const float tau   = softplus_f(tau_kernel[r]);
    const float scale = tau * (1.0f / 64.0f);

    if (w < K_) {
        // ----- expm for k = w -----
        const int  k   = w;
        const bool act = (lane < 25);
        const int  a   = lane / 5;          // tile-row block (rows 4a..4a+3)
        const int  bb  = lane - a * 5;      // tile-col block (cols 4bb..4bb+3)
        float* Arm = sA[k];
        float* Tc  = sT[k];

        float P[4][4];

        if (act) {
            float4 arow[4];
            #pragma unroll
            for (int r4 = 0; r4 < 4; r4++) {
                float4 q = *(const float4*)(g_Q + (k * S_ + 4 * a + r4) * S_ + 4 * bb);
                arow[r4] = make_float4(q.x * scale, q.y * scale, q.z * scale, q.w * scale);
                *(float4*)(Arm + (4 * a + r4) * S_ + 4 * bb) = arow[r4];
            }
            // column-major copy of A into Tc (T starts as A)
            #pragma unroll
            for (int c = 0; c < 4; c++) {
                float4 v = make_float4((&arow[0].x)[c], (&arow[1].x)[c],
                                       (&arow[2].x)[c], (&arow[3].x)[c]);
                *(float4*)(Tc + (4 * bb + c) * S_ + 4 * a) = v;
            }
            #pragma unroll
            for (int r4 = 0; r4 < 4; r4++)
                #pragma unroll
                for (int c = 0; c < 4; c++)
                    P[r4][c] = (&arow[r4].x)[c] +
                               ((4 * a + r4) == (4 * bb + c) ? 1.0f : 0.0f);
        }
        __syncwarp();

        // Taylor: T <- T*A/n ; P += T  (single T buffer, syncwarp fences)
        #pragma unroll 1
        for (int n = 2; n <= NTAY; n++) {
            float acc[4][4];
            if (act) {
                #pragma unroll
                for (int r4 = 0; r4 < 4; r4++)
                    #pragma unroll
                    for (int c = 0; c < 4; c++) acc[r4][c] = 0.0f;
                #pragma unroll
                for (int t = 0; t < S_; t++) {
                    const float4 tv = *(const float4*)(Tc + t * S_ + 4 * a);
                    const float4 av = *(const float4*)(Arm + t * S_ + 4 * bb);
                    const float* tvp = &tv.x;
                    const float* avp = &av.x;
                    #pragma unroll
                    for (int r4 = 0; r4 < 4; r4++)
                        #pragma unroll
                        for (int c = 0; c < 4; c++)
                            acc[r4][c] = fmaf(tvp[r4], avp[c], acc[r4][c]);
                }
            }
            __syncwarp();   // all reads of Tc done before overwrite
            if (act) {
                const float inv = 1.0f / (float)n;
                #pragma unroll
                for (int r4 = 0; r4 < 4; r4++)
                    #pragma unroll
                    for (int c = 0; c < 4; c++) {
                        acc[r4][c] *= inv;
                        P[r4][c] += acc[r4][c];
                    }
                #pragma unroll
                for (int c = 0; c < 4; c++) {
                    float4 v = make_float4(acc[0][c], acc[1][c], acc[2][c], acc[3][c]);
                    *(float4*)(Tc + (4 * bb + c) * S_ + 4 * a) = v;
                }
            }
            __syncwarp();
        }

        // 6 squarings: P <- P*P
        #pragma unroll 1
        for (int q = 0; q < SQN; q++) {
            if (act) {
                #pragma unroll
                for (int r4 = 0; r4 < 4; r4++) {
                    float4 v = make_float4(P[r4][0], P[r4][1], P[r4][2], P[r4][3]);
                    *(float4*)(Arm + (4 * a + r4) * S_ + 4 * bb) = v;
                }
                #pragma unroll
                for (int c = 0; c < 4; c++) {
                    float4 v = make_float4(P[0][c], P[1][c], P[2][c], P[3][c]);
                    *(float4*)(Tc + (4 * bb + c) * S_ + 4 * a) = v;
                }
            }
            __syncwarp();
            if (act) {
                float acc[4][4];
                #pragma unroll
                for (int r4 = 0; r4 < 4; r4++)
                    #pragma unroll
                    for (int c = 0; c < 4; c++) acc[r4][c] = 0.0f;
                #pragma unroll
                for (int t = 0; t < S_; t++) {
                    const float4 tv = *(const float4*)(Tc + t * S_ + 4 * a);
                    const float4 av = *(const float4*)(Arm + t * S_ + 4 * bb);
                    const float* tvp = &tv.x;
                    const float* avp = &av.x;
                    #pragma unroll
                    for (int r4 = 0; r4 < 4; r4++)
                        #pragma unroll
                        for (int c = 0; c < 4; c++)
                            acc[r4][c] = fmaf(tvp[r4], avp[c], acc[r4][c]);
                }
                #pragma unroll
                for (int r4 = 0; r4 < 4; r4++)
                    #pragma unroll
                    for (int c = 0; c < 4; c++) P[r4][c] = acc[r4][c];
            }
            __syncwarp();
        }

        // write result straight into RowTable: RT[row i][k*26 + col e]
        if (act) {
            #pragma unroll
            for (int r4 = 0; r4 < 4; r4++)
                #pragma unroll
                for (int c = 0; c < 4; c++)
                    RT[(4 * a + r4) * ROWW + k * EXT_ + 4 * bb + c] = P[r4][c];
        }
    } else {
        // ----- warps 8-12: fill pad-zero + one-hot region of RT -----
        for (int idx = tid - 256; idx < EXT_ * ROWW; idx += NTHR - 256) {
            const int c = idx / ROWW;
            const int f = idx - c * ROWW;
            const int kk = f / EXT_;
            const int e  = f - kk * EXT_;
            if (c < S_ && e < S_) continue;          // expm warps own these
            RT[idx] = (c >= S_ && e == c) ? 1.0f : 0.0f;
        }
    }
    __syncthreads();

    // ----- streaming copy: 1024 positions x 52 float4 -----
    const int j  = tid % 52;
    const int p0 = tid / 52;                // 0..7
    const float4* RT4 = (const float4*)RT;
    const int* crow = inputs + (size_t)b * L_;
    float4* ob = (float4*)out + (size_t)b * L_ * 52;

    #pragma unroll 4
    for (int p = p0; p < L_; p += 8) {
        const int c = __ldg(crow + p);      // 52-way broadcast, L1-resident
        __stcs(ob + (size_t)p * 52 + j, RT4[c * 52 + j]);
    }
}

// ---------------------------------------------------------------------------
extern "C" void kernel_launch(void* const* d_in, const int* in_sizes, int n_in,
                              void* d_out, int out_size) {
    const int*   inputs       = (const int*)  d_in[0];
    const int*   rate_indices = (const int*)  d_in[1];
    const float* tau_kernel   = (const float*)d_in[2];
    const float* exch         = (const float*)d_in[3];
    const float* freq         = (const float*)d_in[4];
    float*       out          = (float*)d_out;

    (void)in_sizes; (void)n_in; (void)out_size;

    dim3 tb(S_, S_);
    qprep_kernel<<<K_, tb>>>(exch, freq);
    fused_kernel<<<B_, NTHR>>>(inputs, rate_indices, tau_kernel, out);
}